// round 16
// baseline (speedup 1.0000x reference)
#include <cuda_runtime.h>
#include <cuda_fp16.h>
#include <stdint.h>

#define Tt 12
#define Nn 4000
#define Jj 192          // B*T*C
#define BNr 32000       // B*N
#define NJ (Nn*Jj)
#define SPLITK 5
#define ADJ_SCALE 4096.0f
#define ADJ_INV (1.0f/4096.0f)

// ---------------- scratch ----------------
__device__ uint32_t d_XTh32[Jj * 2000];   // x^T: [j][m-pair] packed half2
__device__ float d_XGp[SPLITK * NJ];      // split-K partials of (4096*adj) @ x
__device__ __align__(16) char d_Wall[73728];   // pre-permuted lstm weights (fp16)

// ---------------- helpers ----------------
__device__ __forceinline__ float tanha(float x) {
    float y;
    asm("tanh.approx.f32 %0, %1;" : "=f"(y) : "f"(x));
    return y;
}
__device__ __forceinline__ float siga(float x) {
    return fmaf(0.5f, tanha(0.5f * x), 0.5f);
}
__device__ __forceinline__ uint32_t pack2h(__half a, __half b) {
    __half2 v; v.x = a; v.y = b;
    return *(uint32_t*)&v;
}
__device__ __forceinline__ void hmma(float& d0, float& d1, float& d2, float& d3,
                                     uint32_t a0, uint32_t a1, uint32_t a2, uint32_t a3,
                                     uint32_t b0, uint32_t b1) {
    asm volatile("mma.sync.aligned.m16n8k16.row.col.f32.f16.f16.f32 "
        "{%0,%1,%2,%3}, {%4,%5,%6,%7}, {%8,%9}, {%0,%1,%2,%3};"
        : "+f"(d0), "+f"(d1), "+f"(d2), "+f"(d3)
        : "r"(a0), "r"(a1), "r"(a2), "r"(a3), "r"(b0), "r"(b1));
}

// ---------------- prep: weight permute (fp16) + x transpose/pack ----------------
__global__ void prep_all(const float* __restrict__ x,
                         const float* __restrict__ Wih, const float* __restrict__ Whh) {
    int gid = blockIdx.x * 256 + threadIdx.x;
    if (gid < 16384) {
        int o = gid >> 6, k = gid & 63;
        int gate = o >> 6, h = o & 63;
        int n = (h >> 3) * 32 + gate * 8 + (h & 7);
        *(__half*)(d_Wall +          (n * 72 + k) * 2) = __float2half(Wih[gid]);
        *(__half*)(d_Wall + 36864u + (n * 72 + k) * 2) = __float2half(Whh[gid]);
    }
    if (gid < Jj * 2000) {
        int j = gid / 2000, m2 = gid - j * 2000;
        int bt = j >> 1, c = j & 1;
        size_t base = (size_t)bt * Nn * 2 + c;
        float v0 = x[base + (size_t)(2 * m2) * 2];
        float v1 = x[base + (size_t)(2 * m2 + 1) * 2];
        d_XTh32[gid] = pack2h(__float2half(v0), __float2half(v1));
    }
}

// ---------------- adj GEMM via fp16 mma, 1-term, BM=80, 250 blocks ----------------
#define BTS 40
__global__ __launch_bounds__(256, 2) void gemm_adj_mma(const float* __restrict__ adj) {
    __shared__ __align__(16) __half Ah[80 * BTS];
    __shared__ __align__(16) __half Bh[192 * BTS];
    int tid = threadIdx.x, wid = tid >> 5, lane = tid & 31;
    int g = lane >> 2, t4 = lane & 3;
    int rowb = blockIdx.x * 80;
    int kb0 = blockIdx.y * 800;
    float acc[5][3][4];
#pragma unroll
    for (int mt = 0; mt < 5; mt++)
#pragma unroll
        for (int nt = 0; nt < 3; nt++)
#pragma unroll
            for (int q = 0; q < 4; q++) acc[mt][nt][q] = 0.f;

    for (int it = 0; it < 25; it++) {
        int kb = kb0 + it * 32;
#pragma unroll
        for (int q = 0; q < 5; q++) {            // A: 80 rows x 16 float2, scaled x4096
            int lin = tid + 256 * q;
            int r = lin >> 4, w = lin & 15;
            float2 v = *(const float2*)&adj[(size_t)(rowb + r) * Nn + kb + 2 * w];
            ((uint32_t*)Ah)[r * (BTS/2) + w] =
                pack2h(__float2half(v.x * ADJ_SCALE), __float2half(v.y * ADJ_SCALE));
        }
        int kw = kb >> 1;
#pragma unroll
        for (int q = 0; q < 12; q++) {           // B: 192 rows x 16 words
            int lin = tid + 256 * q;
            int j = lin >> 4, w = lin & 15;
            ((uint32_t*)Bh)[j * (BTS/2) + w] = d_XTh32[j * 2000 + kw + w];
        }
        __syncthreads();
#pragma unroll
        for (int kc = 0; kc < 2; kc++) {
            int kk = kc * 16 + 2 * t4;
            uint32_t ah[5][4];
#pragma unroll
            for (int mt = 0; mt < 5; mt++) {
                const __half* p0 = Ah + (16 * mt + g) * BTS + kk;
                const __half* p1 = Ah + (16 * mt + 8 + g) * BTS + kk;
                ah[mt][0] = *(const uint32_t*)p0;
                ah[mt][1] = *(const uint32_t*)p1;
                ah[mt][2] = *(const uint32_t*)(p0 + 8);
                ah[mt][3] = *(const uint32_t*)(p1 + 8);
            }
#pragma unroll
            for (int nt = 0; nt < 3; nt++) {
                int n = wid * 24 + nt * 8 + g;
                const __half* pb = Bh + n * BTS + kk;
                uint32_t bh0 = *(const uint32_t*)pb, bh1 = *(const uint32_t*)(pb + 8);
#pragma unroll
                for (int mt = 0; mt < 5; mt++)
                    hmma(acc[mt][nt][0], acc[mt][nt][1], acc[mt][nt][2], acc[mt][nt][3],
                         ah[mt][0], ah[mt][1], ah[mt][2], ah[mt][3], bh0, bh1);
            }
        }
        __syncthreads();
    }
    float* outp = d_XGp + (size_t)blockIdx.y * NJ;
#pragma unroll
    for (int mt = 0; mt < 5; mt++) {
#pragma unroll
        for (int nt = 0; nt < 3; nt++) {
            int r0 = rowb + 16 * mt + g;
            int col = wid * 24 + nt * 8 + 2 * t4;
            float2 v0 = {acc[mt][nt][0], acc[mt][nt][1]};
            float2 v1 = {acc[mt][nt][2], acc[mt][nt][3]};
            *(float2*)&outp[r0 * Jj + col] = v0;
            *(float2*)&outp[(r0 + 8) * Jj + col] = v1;
        }
    }
}

// ---------------- fp16 mma LSTM: 64 rows/block, double-buffered, 1 sync/step ----------------
// fp32 cell state + fp32 gate math (precision-critical; f16 c-state failed at 1.16e-3)
#define WTS 72
#define OFF_WIHH 0u
#define OFF_WHHH 36864u
#define OFF_G0 73728u          // 9216 each
#define OFF_G1 82944u
#define OFF_H0 92160u
#define OFF_H1 101376u
#define OFF_BIAS 110592u       // 256 f
#define OFF_WG 111616u         // 128 f
#define OFF_BG 112128u         // 64 f
#define OFF_WO 112384u         // 64 f
#define LSTM_SMEM 112640u

// 1-term pass: acc += A@B.  A tile = this warp's 32-row m-half, warp n-slice wq*64.
__device__ __forceinline__ void mma_pass1(float (*acc)[8][4],
        const __half* Ah, const __half* Bh, int g, int t4, int wq) {
#pragma unroll
    for (int kc = 0; kc < 4; kc++) {
        int kk = kc * 16 + 2 * t4;
        uint32_t ah[2][4];
#pragma unroll
        for (int mt = 0; mt < 2; mt++) {
            const __half* p0 = Ah + (16 * mt + g) * WTS + kk;
            const __half* p1 = Ah + (16 * mt + 8 + g) * WTS + kk;
            ah[mt][0] = *(const uint32_t*)p0;
            ah[mt][1] = *(const uint32_t*)p1;
            ah[mt][2] = *(const uint32_t*)(p0 + 8);
            ah[mt][3] = *(const uint32_t*)(p1 + 8);
        }
#pragma unroll
        for (int np = 0; np < 4; np++) {
            int n0 = wq * 64 + (2 * np) * 8 + g;
            int n1 = n0 + 8;
            const __half* pb0 = Bh + n0 * WTS + kk;
            const __half* pb1 = Bh + n1 * WTS + kk;
            uint32_t b0h0 = *(const uint32_t*)pb0, b0h1 = *(const uint32_t*)(pb0 + 8);
            uint32_t b1h0 = *(const uint32_t*)pb1, b1h1 = *(const uint32_t*)(pb1 + 8);
            float* a00 = acc[0][2 * np];
            float* a10 = acc[1][2 * np];
            float* a01 = acc[0][2 * np + 1];
            float* a11 = acc[1][2 * np + 1];
            hmma(a00[0], a00[1], a00[2], a00[3], ah[0][0], ah[0][1], ah[0][2], ah[0][3], b0h0, b0h1);
            hmma(a10[0], a10[1], a10[2], a10[3], ah[1][0], ah[1][1], ah[1][2], ah[1][3], b0h0, b0h1);
            hmma(a01[0], a01[1], a01[2], a01[3], ah[0][0], ah[0][1], ah[0][2], ah[0][3], b1h0, b1h1);
            hmma(a11[0], a11[1], a11[2], a11[3], ah[1][0], ah[1][1], ah[1][2], ah[1][3], b1h0, b1h1);
        }
    }
}

__global__ __launch_bounds__(256, 2) void lstm_mma(
        const float* __restrict__ Wg,  const float* __restrict__ bg,
        const float* __restrict__ bih, const float* __restrict__ bhh,
        const float* __restrict__ Wout, const float* __restrict__ bout,
        float* __restrict__ out) {
    extern __shared__ __align__(16) char smc[];
    __half* WIHh = (__half*)(smc + OFF_WIHH);
    __half* WHHh = (__half*)(smc + OFF_WHHH);
    __half* Gb[2] = {(__half*)(smc + OFF_G0), (__half*)(smc + OFF_G1)};
    __half* Hb[2] = {(__half*)(smc + OFF_H0), (__half*)(smc + OFF_H1)};
    float* sbias = (float*)(smc + OFF_BIAS);
    float* sWg   = (float*)(smc + OFF_WG);
    float* sbg   = (float*)(smc + OFF_BG);
    float* sWo   = (float*)(smc + OFF_WO);
    float* outp  = (float*)(smc + OFF_G0);   // reused after final MMA (4*68 floats)

    int tid = threadIdx.x, wid = tid >> 5, lane = tid & 31;
    int g = lane >> 2, t4 = lane & 3;
    int wm = wid >> 2, wq = wid & 3;        // m-half (32 rows), n-slice (64 cols)
    int rowb = blockIdx.x * 64;

    {   // linear copy of pre-permuted weight image: 4608 uint4 over 256 threads
        const uint4* src = (const uint4*)d_Wall;
        uint4* dst = (uint4*)smc;
#pragma unroll
        for (int q = 0; q < 18; q++) dst[tid + 256 * q] = src[tid + 256 * q];
    }
    {
        int n = tid;
        int gate = (n >> 3) & 3, h = (n >> 5) * 8 + (n & 7);
        int o = gate * 64 + h;
        sbias[n] = bih[o] + bhh[o];
    }
    if (tid < 128) sWg[tid] = Wg[tid];
    if (tid < 64) { sbg[tid] = bg[tid]; sWo[tid] = Wout[tid]; }

    // per-thread xg registers: thread (row=tid>>2, slot=tid&3) owns steps 3*slot..+2
    int grow = tid >> 2, t4b = tid & 3;
    float xga[6];
    {
        int R = rowb + grow;
        int b = R / Nn, n = R - b * Nn;
        const float* base = d_XGp + (size_t)n * Jj + b * 24;
#pragma unroll
        for (int s = 0; s < 3; s++) {
            int toff = 2 * (3 * t4b + s);
            float2 a = make_float2(0.f, 0.f);
#pragma unroll
            for (int sp = 0; sp < SPLITK; sp++) {
                float2 v = *(const float2*)(base + (size_t)sp * NJ + toff);
                a.x += v.x; a.y += v.y;
            }
            xga[2 * s]     = a.x * ADJ_INV;
            xga[2 * s + 1] = a.y * ADJ_INV;
        }
    }
    __syncthreads();

    float cst[2][8];                         // fp32 cell state: [mt][hg*4 + d]
#pragma unroll
    for (int mt = 0; mt < 2; mt++)
#pragma unroll
        for (int q = 0; q < 8; q++) cst[mt][q] = 0.f;
    float hsv[2][8];                         // fp32 h staging (stored next step)

#pragma unroll
    for (int t = 0; t < Tt; t++) {
        __half* Gc = Gb[t & 1];
        __half* Hc = Hb[t & 1];
        // ---- G tile build into current buffer (xg via width-4 shuffle) ----
        {
            int src = t / 3, sidx = t % 3;
            float xv0 = __shfl_sync(0xffffffffu, xga[2 * sidx], src, 4);
            float xv1 = __shfl_sync(0xffffffffu, xga[2 * sidx + 1], src, 4);
#pragma unroll
            for (int j = 0; j < 8; j++) {
                int k = t4b * 2 + 8 * j;
                float z0 = fmaf(xv0, sWg[2 * k],     fmaf(xv1, sWg[2 * k + 1], sbg[k]));
                float z1 = fmaf(xv0, sWg[2 * k + 2], fmaf(xv1, sWg[2 * k + 3], sbg[k + 1]));
                z0 = fmaxf(z0, 0.f); z1 = fmaxf(z1, 0.f);
                *(uint32_t*)(Gc + grow * WTS + k) =
                    pack2h(__float2half(z0), __float2half(z1));
            }
        }
        // ---- store h(t-1) into current H buffer ----
        if (t > 0) {
#pragma unroll
            for (int mt = 0; mt < 2; mt++)
#pragma unroll
                for (int s = 0; s < 2; s++) {
                    int row = wm * 32 + 16 * mt + 8 * s + g;
#pragma unroll
                    for (int hg = 0; hg < 2; hg++) {
                        int hidx = (2 * wq + hg) * 8 + 2 * t4;
                        *(uint32_t*)(Hc + row * WTS + hidx) =
                            pack2h(__float2half(hsv[mt][hg * 4 + 2 * s]),
                                   __float2half(hsv[mt][hg * 4 + 2 * s + 1]));
                    }
                }
        }
        __syncthreads();                     // single barrier per step
        // ---- MMAs ----
        float acc[2][8][4];
#pragma unroll
        for (int mt = 0; mt < 2; mt++)
#pragma unroll
            for (int nt = 0; nt < 8; nt++)
#pragma unroll
                for (int q = 0; q < 4; q++) acc[mt][nt][q] = 0.f;
        mma_pass1(acc, Gc + wm * 32 * WTS, WIHh, g, t4, wq);
        if (t > 0) mma_pass1(acc, Hc + wm * 32 * WTS, WHHh, g, t4, wq);
        // ---- cell update (fp32 math, tanh.approx.f32) ----
#pragma unroll
        for (int mt = 0; mt < 2; mt++) {
#pragma unroll
            for (int hg = 0; hg < 2; hg++) {
#pragma unroll
                for (int d = 0; d < 4; d++) {
                    int j = d & 1;
                    int nb = wq * 64 + hg * 32 + 2 * t4 + j;
                    float ig = acc[mt][hg * 4 + 0][d] + sbias[nb];
                    float fg = acc[mt][hg * 4 + 1][d] + sbias[nb + 8];
                    float gg = acc[mt][hg * 4 + 2][d] + sbias[nb + 16];
                    float og = acc[mt][hg * 4 + 3][d] + sbias[nb + 24];
                    float cn = siga(fg) * cst[mt][hg * 4 + d] + siga(ig) * tanha(gg);
                    cst[mt][hg * 4 + d] = cn;
                    hsv[mt][hg * 4 + d] = siga(og) * tanha(cn);
                }
            }
        }
        if (t == Tt - 1) {
            // output head partials from hsv (writes overlay G0; MMA(11) read G1/H1)
#pragma unroll
            for (int mt = 0; mt < 2; mt++) {
#pragma unroll
                for (int s = 0; s < 2; s++) {
                    int row = wm * 32 + 16 * mt + 8 * s + g;
                    float c = 0.f;
#pragma unroll
                    for (int hg = 0; hg < 2; hg++) {
                        int hidx = (2 * wq + hg) * 8 + 2 * t4;
                        c = fmaf(hsv[mt][hg * 4 + 2 * s],     sWo[hidx],
                            fmaf(hsv[mt][hg * 4 + 2 * s + 1], sWo[hidx + 1], c));
                    }
                    c += __shfl_down_sync(0xffffffffu, c, 2, 4);
                    c += __shfl_down_sync(0xffffffffu, c, 1, 4);
                    if (t4 == 0) outp[wq * 68 + row] = c;
                }
            }
        }
    }
    __syncthreads();
    if (tid < 64) {
        float s = outp[tid] + outp[68 + tid] + outp[136 + tid] + outp[204 + tid];
        out[rowb + tid] = s + bout[0];
    }
}

// ---------------- launch ----------------
extern "C" void kernel_launch(void* const* d_in, const int* in_sizes, int n_in,
                              void* d_out, int out_size) {
    const float* x    = (const float*)d_in[0];
    const float* adj  = (const float*)d_in[1];
    const float* Wg   = (const float*)d_in[2];
    const float* bg   = (const float*)d_in[3];
    const float* Wih  = (const float*)d_in[4];
    const float* Whh  = (const float*)d_in[5];
    const float* bih  = (const float*)d_in[6];
    const float* bhh  = (const float*)d_in[7];
    const float* Wout = (const float*)d_in[8];
    const float* bout = (const float*)d_in[9];
    float* out = (float*)d_out;

    cudaFuncSetAttribute(lstm_mma, cudaFuncAttributeMaxDynamicSharedMemorySize, LSTM_SMEM);

    prep_all<<<(Jj * 2000 + 255) / 256, 256>>>(x, Wih, Whh);
    dim3 ga(50, SPLITK);
    gemm_adj_mma<<<ga, 256>>>(adj);
    lstm_mma<<<BNr / 64, 256, LSTM_SMEM>>>(Wg, bg, bih, bhh, Wout, bout, out);
}

// round 17
// speedup vs baseline: 1.0187x; 1.0187x over previous
#include <cuda_runtime.h>
#include <cuda_fp16.h>
#include <stdint.h>

#define Tt 12
#define Nn 4000
#define Jj 192          // B*T*C
#define BNr 32000       // B*N
#define NJ (Nn*Jj)
#define SPLITK 5
#define ADJ_SCALE 4096.0f
#define ADJ_INV (1.0f/4096.0f)

// ---------------- scratch ----------------
__device__ uint32_t d_XTh32[Jj * 2000];   // x^T: [j][m-pair] packed half2
__device__ float d_XGp[SPLITK * NJ];      // split-K partials of (4096*adj) @ x
__device__ __align__(16) char d_Wall[73728];   // pre-permuted lstm weights (fp16)

// ---------------- helpers ----------------
__device__ __forceinline__ float tanha(float x) {
    float y;
    asm("tanh.approx.f32 %0, %1;" : "=f"(y) : "f"(x));
    return y;
}
__device__ __forceinline__ float siga(float x) {
    return fmaf(0.5f, tanha(0.5f * x), 0.5f);
}
__device__ __forceinline__ uint32_t pack2h(__half a, __half b) {
    __half2 v; v.x = a; v.y = b;
    return *(uint32_t*)&v;
}
__device__ __forceinline__ void hmma(float& d0, float& d1, float& d2, float& d3,
                                     uint32_t a0, uint32_t a1, uint32_t a2, uint32_t a3,
                                     uint32_t b0, uint32_t b1) {
    asm volatile("mma.sync.aligned.m16n8k16.row.col.f32.f16.f16.f32 "
        "{%0,%1,%2,%3}, {%4,%5,%6,%7}, {%8,%9}, {%0,%1,%2,%3};"
        : "+f"(d0), "+f"(d1), "+f"(d2), "+f"(d3)
        : "r"(a0), "r"(a1), "r"(a2), "r"(a3), "r"(b0), "r"(b1));
}

// ---------------- prep: weight permute (fp16) + x transpose/pack ----------------
__global__ void prep_all(const float* __restrict__ x,
                         const float* __restrict__ Wih, const float* __restrict__ Whh) {
    int gid = blockIdx.x * 256 + threadIdx.x;
    if (gid < 16384) {
        int o = gid >> 6, k = gid & 63;
        int gate = o >> 6, h = o & 63;
        int n = (h >> 3) * 32 + gate * 8 + (h & 7);
        *(__half*)(d_Wall +          (n * 72 + k) * 2) = __float2half(Wih[gid]);
        *(__half*)(d_Wall + 36864u + (n * 72 + k) * 2) = __float2half(Whh[gid]);
    }
    if (gid < Jj * 2000) {
        int j = gid / 2000, m2 = gid - j * 2000;
        int bt = j >> 1, c = j & 1;
        size_t base = (size_t)bt * Nn * 2 + c;
        float v0 = x[base + (size_t)(2 * m2) * 2];
        float v1 = x[base + (size_t)(2 * m2 + 1) * 2];
        d_XTh32[gid] = pack2h(__float2half(v0), __float2half(v1));
    }
}

// ---------------- adj GEMM via fp16 mma, 1-term, BM=80, register-prefetch pipeline ----------------
#define BTS 40
__global__ __launch_bounds__(256, 2) void gemm_adj_mma(const float* __restrict__ adj) {
    __shared__ __align__(16) __half Ah[80 * BTS];
    __shared__ __align__(16) __half Bh[192 * BTS];
    int tid = threadIdx.x, wid = tid >> 5, lane = tid & 31;
    int g = lane >> 2, t4 = lane & 3;
    int rowb = blockIdx.x * 80;
    int kb0 = blockIdx.y * 800;
    float acc[5][3][4];
#pragma unroll
    for (int mt = 0; mt < 5; mt++)
#pragma unroll
        for (int nt = 0; nt < 3; nt++)
#pragma unroll
            for (int q = 0; q < 4; q++) acc[mt][nt][q] = 0.f;

    // addressing for the per-iteration tile loads
    int ar = tid >> 4, aw = tid & 15;        // A: rows ar, ar+16.., words aw (5 chunks via +256)
    float2 pfA[5];
    uint32_t pfB[12];
    // prefetch iteration 0
    {
        int kb = kb0;
#pragma unroll
        for (int q = 0; q < 5; q++) {
            int lin = tid + 256 * q;
            int r = lin >> 4, w = lin & 15;
            pfA[q] = *(const float2*)&adj[(size_t)(rowb + r) * Nn + kb + 2 * w];
        }
        int kw = kb >> 1;
#pragma unroll
        for (int q = 0; q < 12; q++) {
            int lin = tid + 256 * q;
            int j = lin >> 4, w = lin & 15;
            pfB[q] = d_XTh32[j * 2000 + kw + w];
        }
    }

    for (int it = 0; it < 25; it++) {
        // store prefetched regs into smem (fp16 convert for A)
#pragma unroll
        for (int q = 0; q < 5; q++) {
            int lin = tid + 256 * q;
            int r = lin >> 4, w = lin & 15;
            ((uint32_t*)Ah)[r * (BTS/2) + w] =
                pack2h(__float2half(pfA[q].x * ADJ_SCALE), __float2half(pfA[q].y * ADJ_SCALE));
        }
#pragma unroll
        for (int q = 0; q < 12; q++) {
            int lin = tid + 256 * q;
            int j = lin >> 4, w = lin & 15;
            ((uint32_t*)Bh)[j * (BTS/2) + w] = pfB[q];
        }
        __syncthreads();
        // prefetch next iteration (overlaps with compute below)
        if (it < 24) {
            int kb = kb0 + (it + 1) * 32;
#pragma unroll
            for (int q = 0; q < 5; q++) {
                int lin = tid + 256 * q;
                int r = lin >> 4, w = lin & 15;
                pfA[q] = *(const float2*)&adj[(size_t)(rowb + r) * Nn + kb + 2 * w];
            }
            int kw = kb >> 1;
#pragma unroll
            for (int q = 0; q < 12; q++) {
                int lin = tid + 256 * q;
                int j = lin >> 4, w = lin & 15;
                pfB[q] = d_XTh32[j * 2000 + kw + w];
            }
        }
        // compute current tile
#pragma unroll
        for (int kc = 0; kc < 2; kc++) {
            int kk = kc * 16 + 2 * t4;
            uint32_t ah[5][4];
#pragma unroll
            for (int mt = 0; mt < 5; mt++) {
                const __half* p0 = Ah + (16 * mt + g) * BTS + kk;
                const __half* p1 = Ah + (16 * mt + 8 + g) * BTS + kk;
                ah[mt][0] = *(const uint32_t*)p0;
                ah[mt][1] = *(const uint32_t*)p1;
                ah[mt][2] = *(const uint32_t*)(p0 + 8);
                ah[mt][3] = *(const uint32_t*)(p1 + 8);
            }
#pragma unroll
            for (int nt = 0; nt < 3; nt++) {
                int n = wid * 24 + nt * 8 + g;
                const __half* pb = Bh + n * BTS + kk;
                uint32_t bh0 = *(const uint32_t*)pb, bh1 = *(const uint32_t*)(pb + 8);
#pragma unroll
                for (int mt = 0; mt < 5; mt++)
                    hmma(acc[mt][nt][0], acc[mt][nt][1], acc[mt][nt][2], acc[mt][nt][3],
                         ah[mt][0], ah[mt][1], ah[mt][2], ah[mt][3], bh0, bh1);
            }
        }
        __syncthreads();
    }
    float* outp = d_XGp + (size_t)blockIdx.y * NJ;
#pragma unroll
    for (int mt = 0; mt < 5; mt++) {
#pragma unroll
        for (int nt = 0; nt < 3; nt++) {
            int r0 = rowb + 16 * mt + g;
            int col = wid * 24 + nt * 8 + 2 * t4;
            float2 v0 = {acc[mt][nt][0], acc[mt][nt][1]};
            float2 v1 = {acc[mt][nt][2], acc[mt][nt][3]};
            *(float2*)&outp[r0 * Jj + col] = v0;
            *(float2*)&outp[(r0 + 8) * Jj + col] = v1;
        }
    }
}

// ---------------- fp16 mma LSTM: 64 rows/block, double-buffered, 1 sync/step ----------------
// fp32 cell state + fp32 gate math (f16 recurrence failed at 1.16e-3 — keep fp32)
#define WTS 72
#define OFF_WIHH 0u
#define OFF_WHHH 36864u
#define OFF_G0 73728u          // 9216 each
#define OFF_G1 82944u
#define OFF_H0 92160u
#define OFF_H1 101376u
#define OFF_BIAS 110592u       // 256 f
#define OFF_WG 111616u         // 128 f
#define OFF_BG 112128u         // 64 f
#define OFF_WO 112384u         // 64 f
#define LSTM_SMEM 112640u

// 1-term pass: acc += A@B.  A tile = this warp's 32-row m-half, warp n-slice wq*64.
__device__ __forceinline__ void mma_pass1(float (*acc)[8][4],
        const __half* Ah, const __half* Bh, int g, int t4, int wq) {
#pragma unroll
    for (int kc = 0; kc < 4; kc++) {
        int kk = kc * 16 + 2 * t4;
        uint32_t ah[2][4];
#pragma unroll
        for (int mt = 0; mt < 2; mt++) {
            const __half* p0 = Ah + (16 * mt + g) * WTS + kk;
            const __half* p1 = Ah + (16 * mt + 8 + g) * WTS + kk;
            ah[mt][0] = *(const uint32_t*)p0;
            ah[mt][1] = *(const uint32_t*)p1;
            ah[mt][2] = *(const uint32_t*)(p0 + 8);
            ah[mt][3] = *(const uint32_t*)(p1 + 8);
        }
#pragma unroll
        for (int np = 0; np < 4; np++) {
            int n0 = wq * 64 + (2 * np) * 8 + g;
            int n1 = n0 + 8;
            const __half* pb0 = Bh + n0 * WTS + kk;
            const __half* pb1 = Bh + n1 * WTS + kk;
            uint32_t b0h0 = *(const uint32_t*)pb0, b0h1 = *(const uint32_t*)(pb0 + 8);
            uint32_t b1h0 = *(const uint32_t*)pb1, b1h1 = *(const uint32_t*)(pb1 + 8);
            float* a00 = acc[0][2 * np];
            float* a10 = acc[1][2 * np];
            float* a01 = acc[0][2 * np + 1];
            float* a11 = acc[1][2 * np + 1];
            hmma(a00[0], a00[1], a00[2], a00[3], ah[0][0], ah[0][1], ah[0][2], ah[0][3], b0h0, b0h1);
            hmma(a10[0], a10[1], a10[2], a10[3], ah[1][0], ah[1][1], ah[1][2], ah[1][3], b0h0, b0h1);
            hmma(a01[0], a01[1], a01[2], a01[3], ah[0][0], ah[0][1], ah[0][2], ah[0][3], b1h0, b1h1);
            hmma(a11[0], a11[1], a11[2], a11[3], ah[1][0], ah[1][1], ah[1][2], ah[1][3], b1h0, b1h1);
        }
    }
}

__global__ __launch_bounds__(256, 2) void lstm_mma(
        const float* __restrict__ Wg,  const float* __restrict__ bg,
        const float* __restrict__ bih, const float* __restrict__ bhh,
        const float* __restrict__ Wout, const float* __restrict__ bout,
        float* __restrict__ out) {
    extern __shared__ __align__(16) char smc[];
    __half* WIHh = (__half*)(smc + OFF_WIHH);
    __half* WHHh = (__half*)(smc + OFF_WHHH);
    __half* Gb[2] = {(__half*)(smc + OFF_G0), (__half*)(smc + OFF_G1)};
    __half* Hb[2] = {(__half*)(smc + OFF_H0), (__half*)(smc + OFF_H1)};
    float* sbias = (float*)(smc + OFF_BIAS);
    float* sWg   = (float*)(smc + OFF_WG);
    float* sbg   = (float*)(smc + OFF_BG);
    float* sWo   = (float*)(smc + OFF_WO);
    float* outp  = (float*)(smc + OFF_G0);   // reused at t=11 (Gb[0] last read at t=10)

    int tid = threadIdx.x, wid = tid >> 5, lane = tid & 31;
    int g = lane >> 2, t4 = lane & 3;
    int wm = wid >> 2, wq = wid & 3;        // m-half (32 rows), n-slice (64 cols)
    int rowb = blockIdx.x * 64;

    {   // linear copy of pre-permuted weight image: 4608 uint4 over 256 threads
        const uint4* src = (const uint4*)d_Wall;
        uint4* dst = (uint4*)smc;
#pragma unroll
        for (int q = 0; q < 18; q++) dst[tid + 256 * q] = src[tid + 256 * q];
    }
    {
        int n = tid;
        int gate = (n >> 3) & 3, h = (n >> 5) * 8 + (n & 7);
        int o = gate * 64 + h;
        sbias[n] = bih[o] + bhh[o];
    }
    if (tid < 128) sWg[tid] = Wg[tid];
    if (tid < 64) { sbg[tid] = bg[tid]; sWo[tid] = Wout[tid]; }

    // per-thread xg registers: thread (row=tid>>2, slot=tid&3) owns steps 3*slot..+2
    int grow = tid >> 2, t4b = tid & 3;
    float xga[6];
    {
        int R = rowb + grow;
        int b = R / Nn, n = R - b * Nn;
        const float* base = d_XGp + (size_t)n * Jj + b * 24;
#pragma unroll
        for (int s = 0; s < 3; s++) {
            int toff = 2 * (3 * t4b + s);
            float2 a = make_float2(0.f, 0.f);
#pragma unroll
            for (int sp = 0; sp < SPLITK; sp++) {
                float2 v = *(const float2*)(base + (size_t)sp * NJ + toff);
                a.x += v.x; a.y += v.y;
            }
            xga[2 * s]     = a.x * ADJ_INV;
            xga[2 * s + 1] = a.y * ADJ_INV;
        }
    }
    __syncthreads();   // weights + tables ready (also covers xga source reads)

    float cst[2][8];                         // fp32 cell state: [mt][hg*4 + d]
#pragma unroll
    for (int mt = 0; mt < 2; mt++)
#pragma unroll
        for (int q = 0; q < 8; q++) cst[mt][q] = 0.f;
    float hsv[2][8];                         // fp32 h staging

    // G-build helper (macro-like lambda): builds G(tb) into Gb[tb&1]
    auto buildG = [&](int tb) {
        int src = tb / 3, sidx = tb % 3;
        float xv0 = __shfl_sync(0xffffffffu, xga[2 * sidx], src, 4);
        float xv1 = __shfl_sync(0xffffffffu, xga[2 * sidx + 1], src, 4);
        __half* Gd = Gb[tb & 1];
#pragma unroll
        for (int j = 0; j < 8; j++) {
            int k = t4b * 2 + 8 * j;
            float z0 = fmaf(xv0, sWg[2 * k],     fmaf(xv1, sWg[2 * k + 1], sbg[k]));
            float z1 = fmaf(xv0, sWg[2 * k + 2], fmaf(xv1, sWg[2 * k + 3], sbg[k + 1]));
            z0 = fmaxf(z0, 0.f); z1 = fmaxf(z1, 0.f);
            *(uint32_t*)(Gd + grow * WTS + k) = pack2h(__float2half(z0), __float2half(z1));
        }
    };

    buildG(0);

#pragma unroll
    for (int t = 0; t < Tt; t++) {
        __syncthreads();                     // single barrier per step
        __half* Gc = Gb[t & 1];
        __half* Hc = Hb[t & 1];
        float acc[2][8][4];
#pragma unroll
        for (int mt = 0; mt < 2; mt++)
#pragma unroll
            for (int nt = 0; nt < 8; nt++)
#pragma unroll
                for (int q = 0; q < 4; q++) acc[mt][nt][q] = 0.f;
        // G-pass MMAs
        mma_pass1(acc, Gc + wm * 32 * WTS, WIHh, g, t4, wq);
        // build G(t+1) in the MMA shadow (buffer last read at t-1, safe post-barrier)
        if (t < Tt - 1) buildG(t + 1);
        // H-pass MMAs
        if (t > 0) mma_pass1(acc, Hc + wm * 32 * WTS, WHHh, g, t4, wq);
        // ---- cell update (fp32 math, tanh.approx.f32) ----
#pragma unroll
        for (int mt = 0; mt < 2; mt++) {
#pragma unroll
            for (int hg = 0; hg < 2; hg++) {
#pragma unroll
                for (int d = 0; d < 4; d++) {
                    int j = d & 1;
                    int nb = wq * 64 + hg * 32 + 2 * t4 + j;
                    float ig = acc[mt][hg * 4 + 0][d] + sbias[nb];
                    float fg = acc[mt][hg * 4 + 1][d] + sbias[nb + 8];
                    float gg = acc[mt][hg * 4 + 2][d] + sbias[nb + 16];
                    float og = acc[mt][hg * 4 + 3][d] + sbias[nb + 24];
                    float cn = siga(fg) * cst[mt][hg * 4 + d] + siga(ig) * tanha(gg);
                    cst[mt][hg * 4 + d] = cn;
                    hsv[mt][hg * 4 + d] = siga(og) * tanha(cn);
                }
            }
        }
        if (t < Tt - 1) {
            // store h(t) into Hb[(t+1)&1] (last read at t-1, safe post-barrier)
            __half* Hn = Hb[(t + 1) & 1];
#pragma unroll
            for (int mt = 0; mt < 2; mt++)
#pragma unroll
                for (int s = 0; s < 2; s++) {
                    int row = wm * 32 + 16 * mt + 8 * s + g;
#pragma unroll
                    for (int hg = 0; hg < 2; hg++) {
                        int hidx = (2 * wq + hg) * 8 + 2 * t4;
                        *(uint32_t*)(Hn + row * WTS + hidx) =
                            pack2h(__float2half(hsv[mt][hg * 4 + 2 * s]),
                                   __float2half(hsv[mt][hg * 4 + 2 * s + 1]));
                    }
                }
        } else {
            // output head partials from hsv (outp = Gb[0], last read at t=10)
#pragma unroll
            for (int mt = 0; mt < 2; mt++) {
#pragma unroll
                for (int s = 0; s < 2; s++) {
                    int row = wm * 32 + 16 * mt + 8 * s + g;
                    float c = 0.f;
#pragma unroll
                    for (int hg = 0; hg < 2; hg++) {
                        int hidx = (2 * wq + hg) * 8 + 2 * t4;
                        c = fmaf(hsv[mt][hg * 4 + 2 * s],     sWo[hidx],
                            fmaf(hsv[mt][hg * 4 + 2 * s + 1], sWo[hidx + 1], c));
                    }
                    c += __shfl_down_sync(0xffffffffu, c, 2, 4);
                    c += __shfl_down_sync(0xffffffffu, c, 1, 4);
                    if (t4 == 0) outp[wq * 68 + row] = c;
                }
            }
        }
    }
    __syncthreads();
    if (tid < 64) {
        float s = outp[tid] + outp[68 + tid] + outp[136 + tid] + outp[204 + tid];
        out[rowb + tid] = s + bout[0];
    }
}

// ---------------- launch ----------------
extern "C" void kernel_launch(void* const* d_in, const int* in_sizes, int n_in,
                              void* d_out, int out_size) {
    const float* x    = (const float*)d_in[0];
    const float* adj  = (const float*)d_in[1];
    const float* Wg   = (const float*)d_in[2];
    const float* bg   = (const float*)d_in[3];
    const float* Wih  = (const float*)d_in[4];
    const float* Whh  = (const float*)d_in[5];
    const float* bih  = (const float*)d_in[6];
    const float* bhh  = (const float*)d_in[7];
    const float* Wout = (const float*)d_in[8];
    const float* bout = (const float*)d_in[9];
    float* out = (float*)d_out;

    cudaFuncSetAttribute(lstm_mma, cudaFuncAttributeMaxDynamicSharedMemorySize, LSTM_SMEM);

    prep_all<<<(Jj * 2000 + 255) / 256, 256>>>(x, Wih, Whh);
    dim3 ga(50, SPLITK);
    gemm_adj_mma<<<ga, 256>>>(adj);
    lstm_mma<<<BNr / 64, 256, LSTM_SMEM>>>(Wg, bg, bih, bhh, Wout, bout, out);
}